// round 3
// baseline (speedup 1.0000x reference)
#include <cuda_runtime.h>

// ---------------------------------------------------------------------------
// KronFTLinear restructured:
//   out = x @ W^T + b  +  150 * sum_p g_p(x) * (x @ kron(A_p, B_p)^T)
// kron factorization:
//   final[row, 2*o2+i] = 150 * sum_{p,d2} A_p[o2,d2] * Z_i[row, p*2048+d2]
//   Z_i[row, p*2048+d2] = g_p[row] * (B_p[i,0]*x[row,2d2] + B_p[i,1]*x[row,2d2+1])
// A_p = Re ifft2(sparse) = (1/N^2) * (Pm @ Qn^T)  with trig factor matrices.
// idx/gidx width (int32 vs int64) is sniffed at runtime and normalized.
// ---------------------------------------------------------------------------

#define BB 4
#define LL 2048
#define DD 4096
#define OO 4096
#define HALF_D 2048      // IN_P = OUT_P
#define NFP 1000
#define KP 2048          // padded trig-K (2*NFP padded to 2048)
#define ROWS (BB*LL)     // 8192
#define NGATE 819        // P*D//10

// ---------------- scratch (device globals; no allocation allowed) ----------
__device__ int   g_idx32[2*NFP];
__device__ int   g_gidx32[NGATE];
__device__ float g_gate_m[2*DD];
__device__ float g_gate_w[ROWS*2];
__device__ float g_Pm[2ll*HALF_D*KP];     // [p][m][k2]
__device__ float g_Qn[2ll*HALF_D*KP];     // [p][n][k2]
__device__ float g_W2[(long long)HALF_D*DD];   // A stacked: [o2][p*2048+d2]
__device__ float g_Z[2ll*ROWS*DD];        // [i][row][p*2048+d2]

// ---------------- index decode: sniff int32 vs int64 -----------------------
// If the source is int64 (values < 2^31, nonneg), every odd 32-bit word is 0.
// For int32 data the odd words are live permutation values (can't all be 0).
// Sniff uses only the first NFP words -> in-bounds for either width.
__global__ void k_decode_idx(const int* __restrict__ idx_raw,
                             const int* __restrict__ gidx_raw) {
    __shared__ int nz;
    if (threadIdx.x == 0) nz = 0;
    __syncthreads();
    for (int k = threadIdx.x; k < NFP/2; k += 256)
        if (idx_raw[2*k + 1] != 0) atomicAdd(&nz, 1);
    __syncthreads();
    bool is64 = (nz == 0);
    for (int k = threadIdx.x; k < 2*NFP; k += 256)
        g_idx32[k] = is64 ? idx_raw[2*k] : idx_raw[k];
    for (int k = threadIdx.x; k < NGATE; k += 256)
        g_gidx32[k] = is64 ? gidx_raw[2*k] : gidx_raw[k];
}

// ---------------- gate matrix: gate_m[e,d] = (1/8192) sum_k (+-)g_k cos(2*pi*d*c_k/4096)
__global__ void k_gate_m(const float* __restrict__ gate_param) {
    __shared__ float tab[DD];          // cos(2*pi*t/4096)
    __shared__ int   gc[NGATE];
    __shared__ float gg[NGATE], gs[NGATE];
    for (int t = threadIdx.x; t < DD; t += 256)
        tab[t] = cospif(t * (1.0f/2048.0f));
    for (int k = threadIdx.x; k < NGATE; k += 256) {
        int v = g_gidx32[k];
        int r = v >> 12;               // / 4096
        gc[k] = v & 4095;
        float g = gate_param[k];
        gg[k] = g;
        gs[k] = r ? -g : g;            // e=1 row flips sign when r=1
    }
    __syncthreads();
    int d = blockIdx.x * 256 + threadIdx.x;
    float a0 = 0.f, a1 = 0.f;
    for (int k = 0; k < NGATE; k++) {
        int t = (d * gc[k]) & 4095;
        float co = tab[t];
        a0 += gg[k] * co;
        a1 += gs[k] * co;
    }
    g_gate_m[d]      = a0 * (1.0f/8192.0f);
    g_gate_m[DD + d] = a1 * (1.0f/8192.0f);
}

// ---------------- gate weights: softmax over 2 logits per row --------------
__global__ void k_gate_w(const float* __restrict__ x) {
    int row = blockIdx.x;
    const float* xr = x + (long long)row * DD;
    float t0 = 0.f, t1 = 0.f;
    for (int d = threadIdx.x; d < DD; d += 128) {
        float xv = xr[d];
        t0 += xv * g_gate_m[d];
        t1 += xv * g_gate_m[DD + d];
    }
    __shared__ float s0[128], s1[128];
    s0[threadIdx.x] = t0; s1[threadIdx.x] = t1;
    __syncthreads();
    for (int o = 64; o > 0; o >>= 1) {
        if (threadIdx.x < o) {
            s0[threadIdx.x] += s0[threadIdx.x + o];
            s1[threadIdx.x] += s1[threadIdx.x + o];
        }
        __syncthreads();
    }
    if (threadIdx.x == 0) {
        float dlt = s1[0] - s0[0];
        float g1 = 1.0f / (1.0f + expf(-dlt));
        g_gate_w[row*2 + 0] = 1.0f - g1;
        g_gate_w[row*2 + 1] = g1;
    }
}

// ---------------- trig factor matrices for A_p = (1/N^2) Pm @ Qn^T ---------
// Pm[p][v][k]     = s_k * cos(2*pi*(v*r_k mod 2048)/2048)
// Pm[p][v][1000+k]= s_k * sin(...)
// Qn[p][v][k]     =        cos(2*pi*(v*c_k mod 2048)/2048)
// Qn[p][v][1000+k]=       -sin(...)
// k2 in [2000,2048) zero-padded on both sides.
__global__ void k_fill_trig(const float* __restrict__ spectrum) {
    __shared__ float tc[HALF_D], ts[HALF_D];
    __shared__ int   rr[NFP], cc[NFP];
    __shared__ float ss[NFP];
    int p = blockIdx.y;
    for (int t = threadIdx.x; t < HALF_D; t += 256) {
        float s, c;
        sincospif(t * (1.0f/1024.0f), &s, &c);
        tc[t] = c; ts[t] = s;
    }
    for (int k = threadIdx.x; k < NFP; k += 256) {
        int v = g_idx32[p*NFP + k];
        rr[k] = v >> 11;               // / 2048
        cc[k] = v & 2047;
        ss[k] = spectrum[p*NFP + k];
    }
    __syncthreads();
    int v0 = blockIdx.x * 8;
    for (int vi = 0; vi < 8; vi++) {
        int v = v0 + vi;
        long long base = ((long long)(p*HALF_D + v)) * KP;
        for (int k = threadIdx.x; k < NFP; k += 256) {
            int tm = (v * rr[k]) & 2047;
            int tn = (v * cc[k]) & 2047;
            float s = ss[k];
            g_Pm[base + k]        = s * tc[tm];
            g_Pm[base + NFP + k]  = s * ts[tm];
            g_Qn[base + k]        = tc[tn];
            g_Qn[base + NFP + k]  = -ts[tn];
        }
        for (int k = 2*NFP + threadIdx.x; k < KP; k += 256) {
            g_Pm[base + k] = 0.f;
            g_Qn[base + k] = 0.f;
        }
    }
}

// ---------------- Z build: gated 2x2 pair mix ------------------------------
__global__ void k_build_z(const float* __restrict__ x,
                          const float* __restrict__ Blist) {
    long long gid = (long long)blockIdx.x * 256 + threadIdx.x;
    int row = (int)(gid >> 11);
    int d2  = (int)(gid & 2047);
    float2 xv = ((const float2*)x)[(long long)row * HALF_D + d2];
    float g0 = g_gate_w[row*2 + 0];
    float g1 = g_gate_w[row*2 + 1];
    // B_list[p][i][j] = Blist[p*4 + i*2 + j]
    float y00 = Blist[0]*xv.x + Blist[1]*xv.y;  // p=0, i=0
    float y01 = Blist[2]*xv.x + Blist[3]*xv.y;  // p=0, i=1
    float y10 = Blist[4]*xv.x + Blist[5]*xv.y;  // p=1, i=0
    float y11 = Blist[6]*xv.x + Blist[7]*xv.y;  // p=1, i=1
    long long base = (long long)row * DD + d2;
    const long long IOFF = (long long)ROWS * DD;
    g_Z[base]                 = g0 * y00;
    g_Z[base + HALF_D]        = g1 * y10;
    g_Z[IOFF + base]          = g0 * y01;
    g_Z[IOFF + base + HALF_D] = g1 * y11;
}

// ---------------- generic tiled SGEMM: C = alpha * A @ B^T (+bias)(+=C) ----
// A: [M x K] row-major (lda elems), B: [N x K] row-major.
// Output element (m, n) of batch z written at C[m*ldc + n*cstride + z*czoff].
// Requires M,N multiples of 128 and K multiple of 16 (true for all calls).
#define BM 128
#define BN 128
#define BK 16
__global__ __launch_bounds__(256) void sgemm(
    int M, int N, int K,
    const float* __restrict__ A, int lda, long long strideAz,
    const float* __restrict__ Bm, int ldb, long long strideBz,
    float* __restrict__ C, int ldc, int cstride, int czoff,
    const float* __restrict__ bias, float alpha, int accumulate)
{
    __shared__ float As[BK][BM];
    __shared__ float Bs[BK][BN];
    int z = blockIdx.z;
    const float* Ab = A + (long long)z*strideAz + (long long)blockIdx.y*BM*lda;
    const float* Bb = Bm + (long long)z*strideBz + (long long)blockIdx.x*BN*ldb;
    int tid = threadIdx.x;
    int lr = tid >> 2;            // 0..63
    int lc = (tid & 3) * 4;       // 0,4,8,12
    int ty = tid >> 4, tx = tid & 15;
    float acc[8][8];
    #pragma unroll
    for (int i = 0; i < 8; i++)
        #pragma unroll
        for (int j = 0; j < 8; j++) acc[i][j] = 0.f;

    for (int k0 = 0; k0 < K; k0 += BK) {
        #pragma unroll
        for (int h = 0; h < 2; h++) {
            int r = lr + h*64;
            float4 va = *(const float4*)(Ab + (long long)r*lda + k0 + lc);
            As[lc+0][r] = va.x; As[lc+1][r] = va.y;
            As[lc+2][r] = va.z; As[lc+3][r] = va.w;
            float4 vb = *(const float4*)(Bb + (long long)r*ldb + k0 + lc);
            Bs[lc+0][r] = vb.x; Bs[lc+1][r] = vb.y;
            Bs[lc+2][r] = vb.z; Bs[lc+3][r] = vb.w;
        }
        __syncthreads();
        #pragma unroll
        for (int kk = 0; kk < BK; kk++) {
            float ra[8], rb[8];
            *(float4*)&ra[0] = *(const float4*)&As[kk][ty*8];
            *(float4*)&ra[4] = *(const float4*)&As[kk][ty*8 + 4];
            *(float4*)&rb[0] = *(const float4*)&Bs[kk][tx*8];
            *(float4*)&rb[4] = *(const float4*)&Bs[kk][tx*8 + 4];
            #pragma unroll
            for (int i = 0; i < 8; i++)
                #pragma unroll
                for (int j = 0; j < 8; j++)
                    acc[i][j] += ra[i] * rb[j];
        }
        __syncthreads();
    }

    long long mbase = (long long)blockIdx.y*BM + ty*8;
    int nbase = blockIdx.x*BN + tx*8;
    #pragma unroll
    for (int i = 0; i < 8; i++) {
        float* crow = C + (mbase + i) * (long long)ldc;
        #pragma unroll
        for (int j = 0; j < 8; j++) {
            int col = nbase + j;
            float v = acc[i][j] * alpha;
            if (bias) v += bias[col];
            float* cp = crow + (long long)col*cstride + (long long)z*czoff;
            if (accumulate) v += *cp;
            *cp = v;
        }
    }
}

// ---------------------------------------------------------------------------
extern "C" void kernel_launch(void* const* d_in, const int* in_sizes, int n_in,
                              void* d_out, int out_size) {
    const float* x          = (const float*)d_in[0];
    const float* base_w     = (const float*)d_in[1];
    const float* base_b     = (const float*)d_in[2];
    const float* spectrum   = (const float*)d_in[3];
    const float* Blist      = (const float*)d_in[4];
    const float* gate_param = (const float*)d_in[5];
    const int*   idx_raw    = (const int*)d_in[6];
    const int*   gidx_raw   = (const int*)d_in[7];
    float* out = (float*)d_out;
    (void)in_sizes; (void)n_in; (void)out_size;

    float *pPm, *pQn, *pW2, *pZ;
    cudaGetSymbolAddress((void**)&pPm, g_Pm);
    cudaGetSymbolAddress((void**)&pQn, g_Qn);
    cudaGetSymbolAddress((void**)&pW2, g_W2);
    cudaGetSymbolAddress((void**)&pZ,  g_Z);

    // 0. normalize index dtypes (int32 vs int64 sniff)
    k_decode_idx<<<1, 256>>>(idx_raw, gidx_raw);
    // 1. gate matrix (tiny)
    k_gate_m<<<16, 256>>>(gate_param);
    // 2. gate weights per row
    k_gate_w<<<ROWS, 128>>>(x);
    // 3. trig factor matrices for A
    k_fill_trig<<<dim3(256, 2), 256>>>(spectrum);
    // 4. A_p = (1/2048^2) * Pm @ Qn^T  ->  W2[o2][p*2048+d2]   (M=N=2048, K=2048, z=p)
    sgemm<<<dim3(16, 16, 2), 256>>>(
        HALF_D, HALF_D, KP,
        pPm, KP, (long long)HALF_D*KP,
        pQn, KP, (long long)HALF_D*KP,
        pW2, DD, 1, HALF_D,
        nullptr, 1.0f/4194304.0f, 0);
    // 5. gated pair-mixed inputs Z
    k_build_z<<<(ROWS*HALF_D)/256, 256>>>(x, Blist);
    // 6. delta part: out[row, 2n+z] = 150 * (Z_z @ W2^T)   (M=8192, N=2048, K=4096, z=i)
    sgemm<<<dim3(16, 64, 2), 256>>>(
        ROWS, HALF_D, DD,
        pZ, DD, (long long)ROWS*DD,
        pW2, DD, 0ll,
        out, OO, 2, 1,
        nullptr, 150.0f, 0);
    // 7. base linear accumulated on top: out += x @ W^T + b  (M=8192, N=4096, K=4096)
    sgemm<<<dim3(32, 64, 1), 256>>>(
        ROWS, OO, DD,
        x, DD, 0ll,
        base_w, DD, 0ll,
        out, OO, 1, 0,
        base_b, 1.0f, 1);
}

// round 5
// speedup vs baseline: 3.5407x; 3.5407x over previous
#include <cuda_runtime.h>
#include <cuda_bf16.h>
#include <cstdint>

// ---------------------------------------------------------------------------
// KronFTLinear with Ampere-class bf16 tensor-core GEMMs (mma.sync m16n8k16,
// legal on plain sm_103 PTX target — tcgen05 requires the 'a' target which
// this toolchain does not emit).
//
//   out = x @ W^T + b  +  150 * sum_p g_p(x) * (x @ kron(A_p, B_p)^T)
//   final[row, 2*o2+i] = 150 * sum_{p,d2} A_p[o2,d2] * Z_i[row, p*2048+d2]
//   A_p = Re ifft2(sparse) = (1/N^2) * (Pm @ Qn^T)   (trig factor GEMM)
//
// All GEMMs run in bf16 with fp32 accum using the bf16x3 split trick:
//   x = hi + lo (both bf16);  A' = [Ah|Al|Ah], B' = [Bh|Bh|Bl]  (K' = 3K)
//   => C = Ah*Bh + Al*Bh + Ah*Bl  (error ~ lo*lo ~ 2^-16, fp32-like)
// ---------------------------------------------------------------------------

#define DD 4096
#define OO 4096
#define HALF_D 2048
#define NFP 1000
#define ROWS 8192
#define NGATE 819
#define K3 (3*DD)        // 12288
#define K3T (3*HALF_D)   // 6144

typedef long long ll;

// ---------------- device scratch (no allocation allowed) -------------------
__device__ int   g_idx32[2*NFP];
__device__ int   g_gidx32[NGATE];
__device__ float g_gate_m[2*DD];
__device__ float g_gate_w[ROWS*2];
__device__ float g_W2[(ll)HALF_D*DD];             // fp32 A-matrix stack
__device__ __nv_bfloat16 g_Pms[2ll*HALF_D*K3T];   // split trig (A-layout)
__device__ __nv_bfloat16 g_Qns[2ll*HALF_D*K3T];   // split trig (B-layout)
__device__ __nv_bfloat16 g_W2s[(ll)HALF_D*K3];    // split W2 (B-layout)
__device__ __nv_bfloat16 g_Zs[2ll*ROWS*K3];       // split Z  (A-layout)
__device__ __nv_bfloat16 g_xs[(ll)ROWS*K3];       // split x  (A-layout)
__device__ __nv_bfloat16 g_ws[(ll)OO*K3];         // split base_w (B-layout)

// ---------------- PTX helpers ----------------------------------------------
__device__ __forceinline__ uint32_t smem_u32(const void* p) {
    uint32_t a;
    asm("{ .reg .u64 t; cvta.to.shared.u64 t, %1; cvt.u32.u64 %0, t; }" : "=r"(a) : "l"(p));
    return a;
}
#define CP_ASYNC16(dst, src) \
    asm volatile("cp.async.cg.shared.global [%0], [%1], 16;" :: "r"(dst), "l"(src) : "memory")
#define CP_COMMIT() asm volatile("cp.async.commit_group;" ::: "memory")

#define LDSM_X4(r0, r1, r2, r3, addr) \
    asm volatile("ldmatrix.sync.aligned.m8n8.x4.shared.b16 {%0,%1,%2,%3}, [%4];" \
        : "=r"(r0), "=r"(r1), "=r"(r2), "=r"(r3) : "r"(addr))

#define MMA16816(c, a, b) \
    asm volatile("mma.sync.aligned.m16n8k16.row.col.f32.bf16.bf16.f32 " \
        "{%0,%1,%2,%3}, {%4,%5,%6,%7}, {%8,%9}, {%0,%1,%2,%3};" \
        : "+f"((c)[0]), "+f"((c)[1]), "+f"((c)[2]), "+f"((c)[3]) \
        : "r"((a)[0]), "r"((a)[1]), "r"((a)[2]), "r"((a)[3]), \
          "r"((b)[0]), "r"((b)[1]))

// ---------------- index decode: sniff int32 vs int64 -----------------------
__global__ void k_decode_idx(const int* __restrict__ idx_raw,
                             const int* __restrict__ gidx_raw) {
    __shared__ int nz;
    if (threadIdx.x == 0) nz = 0;
    __syncthreads();
    for (int k = threadIdx.x; k < NFP/2; k += 256)
        if (idx_raw[2*k + 1] != 0) atomicAdd(&nz, 1);
    __syncthreads();
    bool is64 = (nz == 0);
    for (int k = threadIdx.x; k < 2*NFP; k += 256)
        g_idx32[k] = is64 ? idx_raw[2*k] : idx_raw[k];
    for (int k = threadIdx.x; k < NGATE; k += 256)
        g_gidx32[k] = is64 ? gidx_raw[2*k] : gidx_raw[k];
}

// ---------------- gate matrix ----------------------------------------------
__global__ void k_gate_m(const float* __restrict__ gate_param) {
    __shared__ float tab[DD];
    __shared__ int   gc[NGATE];
    __shared__ float gg[NGATE], gs[NGATE];
    for (int t = threadIdx.x; t < DD; t += 256)
        tab[t] = cospif(t * (1.0f/2048.0f));
    for (int k = threadIdx.x; k < NGATE; k += 256) {
        int v = g_gidx32[k];
        int r = v >> 12;
        gc[k] = v & 4095;
        float g = gate_param[k];
        gg[k] = g;
        gs[k] = r ? -g : g;
    }
    __syncthreads();
    int d = blockIdx.x * 256 + threadIdx.x;
    float a0 = 0.f, a1 = 0.f;
    for (int k = 0; k < NGATE; k++) {
        int t = (d * gc[k]) & 4095;
        float co = tab[t];
        a0 += gg[k] * co;
        a1 += gs[k] * co;
    }
    g_gate_m[d]      = a0 * (1.0f/8192.0f);
    g_gate_m[DD + d] = a1 * (1.0f/8192.0f);
}

// ---------------- gate weights ---------------------------------------------
__global__ void k_gate_w(const float* __restrict__ x) {
    int row = blockIdx.x;
    const float* xr = x + (ll)row * DD;
    float t0 = 0.f, t1 = 0.f;
    for (int d = threadIdx.x; d < DD; d += 128) {
        float xv = xr[d];
        t0 += xv * g_gate_m[d];
        t1 += xv * g_gate_m[DD + d];
    }
    __shared__ float s0[128], s1[128];
    s0[threadIdx.x] = t0; s1[threadIdx.x] = t1;
    __syncthreads();
    for (int o = 64; o > 0; o >>= 1) {
        if (threadIdx.x < o) {
            s0[threadIdx.x] += s0[threadIdx.x + o];
            s1[threadIdx.x] += s1[threadIdx.x + o];
        }
        __syncthreads();
    }
    if (threadIdx.x == 0) {
        float g1 = 1.0f / (1.0f + expf(-(s1[0] - s0[0])));
        g_gate_w[row*2 + 0] = 1.0f - g1;
        g_gate_w[row*2 + 1] = g1;
    }
}

// ---------------- split-write helpers --------------------------------------
// A-layout row of width 3K: [hi | lo | hi];  B-layout: [hi | hi | lo]
__device__ __forceinline__ void wr_splitA(__nv_bfloat16* d, ll base, int K, int col, float v) {
    __nv_bfloat16 h = __float2bfloat16(v);
    __nv_bfloat16 l = __float2bfloat16(v - __bfloat162float(h));
    d[base + col] = h; d[base + K + col] = l; d[base + 2*K + col] = h;
}
__device__ __forceinline__ void wr_splitB(__nv_bfloat16* d, ll base, int K, int col, float v) {
    __nv_bfloat16 h = __float2bfloat16(v);
    __nv_bfloat16 l = __float2bfloat16(v - __bfloat162float(h));
    d[base + col] = h; d[base + K + col] = h; d[base + 2*K + col] = l;
}

// ---------------- trig factors, written directly in split bf16 -------------
__global__ void k_fill_trig(const float* __restrict__ spectrum) {
    __shared__ float tc[HALF_D], ts[HALF_D];
    __shared__ int   rr[NFP], cc[NFP];
    __shared__ float ss[NFP];
    int p = blockIdx.y;
    for (int t = threadIdx.x; t < HALF_D; t += 256) {
        float s, c;
        sincospif(t * (1.0f/1024.0f), &s, &c);
        tc[t] = c; ts[t] = s;
    }
    for (int k = threadIdx.x; k < NFP; k += 256) {
        int v = g_idx32[p*NFP + k];
        rr[k] = v >> 11;
        cc[k] = v & 2047;
        ss[k] = spectrum[p*NFP + k];
    }
    __syncthreads();
    int v0 = blockIdx.x * 8;
    for (int vi = 0; vi < 8; vi++) {
        int v = v0 + vi;
        ll base = ((ll)(p*HALF_D + v)) * K3T;
        for (int k = threadIdx.x; k < NFP; k += 256) {
            int tm = (v * rr[k]) & 2047;
            int tn = (v * cc[k]) & 2047;
            float s = ss[k];
            wr_splitA(g_Pms, base, HALF_D, k,        s * tc[tm]);
            wr_splitA(g_Pms, base, HALF_D, NFP + k,  s * ts[tm]);
            wr_splitB(g_Qns, base, HALF_D, k,        tc[tn]);
            wr_splitB(g_Qns, base, HALF_D, NFP + k, -ts[tn]);
        }
        for (int k = 2*NFP + threadIdx.x; k < HALF_D; k += 256) {
            __nv_bfloat16 z = __float2bfloat16(0.f);
            g_Pms[base + k] = z; g_Pms[base + HALF_D + k] = z; g_Pms[base + 2*HALF_D + k] = z;
            g_Qns[base + k] = z; g_Qns[base + HALF_D + k] = z; g_Qns[base + 2*HALF_D + k] = z;
        }
    }
}

// ---------------- generic fp32 -> split bf16 (rows of 4096) ----------------
__global__ void k_split(const float* __restrict__ src, __nv_bfloat16* __restrict__ dst,
                        ll n, int hi2blk, int loblk) {
    ll i = (ll)blockIdx.x * 256 + threadIdx.x;
    if (i >= n) return;
    ll m = i >> 12;
    int k = (int)(i & 4095);
    float v = src[i];
    __nv_bfloat16 h = __float2bfloat16(v);
    __nv_bfloat16 l = __float2bfloat16(v - __bfloat162float(h));
    ll base = m * K3;
    dst[base + k] = h;
    dst[base + (ll)hi2blk*DD + k] = h;
    dst[base + (ll)loblk*DD + k]  = l;
}

// ---------------- Z build directly in split bf16 ---------------------------
__global__ void k_build_z(const float* __restrict__ x, const float* __restrict__ Blist) {
    ll gid = (ll)blockIdx.x * 256 + threadIdx.x;
    int row = (int)(gid >> 11);
    int d2  = (int)(gid & 2047);
    float2 xv = ((const float2*)x)[(ll)row * HALF_D + d2];
    float g0 = g_gate_w[row*2 + 0];
    float g1 = g_gate_w[row*2 + 1];
    float y00 = g0 * (Blist[0]*xv.x + Blist[1]*xv.y);   // i=0, p=0
    float y01 = g0 * (Blist[2]*xv.x + Blist[3]*xv.y);   // i=1, p=0
    float y10 = g1 * (Blist[4]*xv.x + Blist[5]*xv.y);   // i=0, p=1
    float y11 = g1 * (Blist[6]*xv.x + Blist[7]*xv.y);   // i=1, p=1
    const ll IOFF = (ll)ROWS * K3;
    ll b0 = (ll)row * K3;
    wr_splitA(g_Zs, b0,        DD, d2,          y00);
    wr_splitA(g_Zs, b0,        DD, HALF_D + d2, y10);
    wr_splitA(g_Zs, IOFF + b0, DD, d2,          y01);
    wr_splitA(g_Zs, IOFF + b0, DD, HALF_D + d2, y11);
}

// ---------------- bf16 tensor-core GEMM: C = alpha * A @ B^T (+bias)(+=C) --
// A:[M x Kp] bf16 row-major, B:[N x Kp] bf16 row-major. 128x128x32 CTA tile,
// 8 warps each computing 64x32 via mma.sync m16n8k16, cp.async double buffer.
// Output element (m,n,z) at C[m*ldc + n*cstride + z*czoff] (fp32).
#define ASTR 40                // smem row stride in bf16 (80B, conflict-free)
#define STG_B (128*ASTR)       // bf16 elems per stage

__global__ __launch_bounds__(256, 2)
void tgemm(const __nv_bfloat16* __restrict__ A, int lda, ll sAz,
           const __nv_bfloat16* __restrict__ B, int ldb, ll sBz,
           float* __restrict__ C, int ldc, int cstride, int czoff,
           const float* __restrict__ bias, float alpha, int accumulate, int Kp)
{
    __shared__ __nv_bfloat16 sA[2*STG_B];
    __shared__ __nv_bfloat16 sB[2*STG_B];
    uint32_t aB = smem_u32(sA), bB = smem_u32(sB);
    int tid = threadIdx.x, wid = tid >> 5, lane = tid & 31;
    int warpM = wid >> 2;          // 0..1  (64 rows)
    int warpN = wid & 3;           // 0..3  (32 cols)
    int z = blockIdx.z;
    ll m0 = (ll)blockIdx.x * 128;
    ll n0 = (ll)blockIdx.y * 128;
    const __nv_bfloat16* Ab = A + (ll)z*sAz + m0*lda;
    const __nv_bfloat16* Bb = B + (ll)z*sBz + n0*ldb;

    float acc[4][4][4];
    #pragma unroll
    for (int i = 0; i < 4; i++)
        #pragma unroll
        for (int j = 0; j < 4; j++)
            #pragma unroll
            for (int q = 0; q < 4; q++) acc[i][j][q] = 0.f;

    // per-thread gmem load coords: chunk c = tid + 256*i, row=c>>2, col=(c&3)*8
    int ldr = tid >> 2;
    int ldc8 = (tid & 3) * 8;

    // ldmatrix lane geometry
    int aRow = warpM*64 + (lane & 15);
    int aCsel = (lane >> 4) * 8;
    int bRowOff = (lane & 7) + ((lane >> 4) << 3);
    int bCsel = ((lane >> 3) & 1) * 8;

    int NP = Kp >> 5;   // number of BK=32 chunks

    // prologue: stage 0
    {
        uint32_t da = aB + ldr*80 + ldc8*2;
        uint32_t db = bB + ldr*80 + ldc8*2;
        CP_ASYNC16(da,        Ab + (ll)ldr*lda + ldc8);
        CP_ASYNC16(db,        Bb + (ll)ldr*ldb + ldc8);
        CP_ASYNC16(da + 64*80, Ab + (ll)(ldr+64)*lda + ldc8);
        CP_ASYNC16(db + 64*80, Bb + (ll)(ldr+64)*ldb + ldc8);
        CP_COMMIT();
    }

    for (int kc = 0; kc < NP; kc++) {
        int st = kc & 1;
        if (kc + 1 < NP) {
            int k0 = (kc + 1) * 32;
            uint32_t so = ((kc + 1) & 1) * (STG_B*2);
            uint32_t da = aB + so + ldr*80 + ldc8*2;
            uint32_t db = bB + so + ldr*80 + ldc8*2;
            CP_ASYNC16(da,        Ab + (ll)ldr*lda + k0 + ldc8);
            CP_ASYNC16(db,        Bb + (ll)ldr*ldb + k0 + ldc8);
            CP_ASYNC16(da + 64*80, Ab + (ll)(ldr+64)*lda + k0 + ldc8);
            CP_ASYNC16(db + 64*80, Bb + (ll)(ldr+64)*ldb + k0 + ldc8);
            CP_COMMIT();
            asm volatile("cp.async.wait_group 1;" ::: "memory");
        } else {
            asm volatile("cp.async.wait_group 0;" ::: "memory");
        }
        __syncthreads();

        uint32_t sao = aB + st * (STG_B*2);
        uint32_t sbo = bB + st * (STG_B*2);
        #pragma unroll
        for (int ks = 0; ks < 32; ks += 16) {
            uint32_t af[4][4];
            #pragma unroll
            for (int mi = 0; mi < 4; mi++) {
                uint32_t ad = sao + (uint32_t)(aRow + mi*16)*80 + (uint32_t)(ks + aCsel)*2;
                LDSM_X4(af[mi][0], af[mi][1], af[mi][2], af[mi][3], ad);
            }
            uint32_t bf[4][2];
            #pragma unroll
            for (int nj = 0; nj < 2; nj++) {
                uint32_t bd = sbo + (uint32_t)(warpN*32 + nj*16 + bRowOff)*80
                                  + (uint32_t)(ks + bCsel)*2;
                uint32_t r0, r1, r2, r3;
                LDSM_X4(r0, r1, r2, r3, bd);
                bf[nj*2][0] = r0; bf[nj*2][1] = r1;
                bf[nj*2+1][0] = r2; bf[nj*2+1][1] = r3;
            }
            #pragma unroll
            for (int mi = 0; mi < 4; mi++)
                #pragma unroll
                for (int ni = 0; ni < 4; ni++)
                    MMA16816(acc[mi][ni], af[mi], bf[ni]);
        }
        __syncthreads();
    }

    // epilogue
    int gID = lane >> 2, tig = lane & 3;
    #pragma unroll
    for (int mi = 0; mi < 4; mi++) {
        #pragma unroll
        for (int h = 0; h < 2; h++) {
            ll row = m0 + warpM*64 + mi*16 + gID + h*8;
            float* crow = C + row * (ll)ldc + (ll)z * czoff;
            #pragma unroll
            for (int ni = 0; ni < 4; ni++) {
                ll col0 = n0 + warpN*32 + ni*8 + tig*2;
                #pragma unroll
                for (int q = 0; q < 2; q++) {
                    ll col = col0 + q;
                    float v = acc[mi][ni][h*2 + q] * alpha;
                    if (bias) v += bias[col];
                    float* cp = crow + col * cstride;
                    if (accumulate) v += *cp;
                    *cp = v;
                }
            }
        }
    }
}

// ---------------------------------------------------------------------------
extern "C" void kernel_launch(void* const* d_in, const int* in_sizes, int n_in,
                              void* d_out, int out_size) {
    const float* x          = (const float*)d_in[0];
    const float* base_w     = (const float*)d_in[1];
    const float* base_b     = (const float*)d_in[2];
    const float* spectrum   = (const float*)d_in[3];
    const float* Blist      = (const float*)d_in[4];
    const float* gate_param = (const float*)d_in[5];
    const int*   idx_raw    = (const int*)d_in[6];
    const int*   gidx_raw   = (const int*)d_in[7];
    float* out = (float*)d_out;
    (void)in_sizes; (void)n_in; (void)out_size;

    float *pW2;
    __nv_bfloat16 *pPms, *pQns, *pW2s, *pZs, *pxs, *pws;
    cudaGetSymbolAddress((void**)&pW2,  g_W2);
    cudaGetSymbolAddress((void**)&pPms, g_Pms);
    cudaGetSymbolAddress((void**)&pQns, g_Qns);
    cudaGetSymbolAddress((void**)&pW2s, g_W2s);
    cudaGetSymbolAddress((void**)&pZs,  g_Zs);
    cudaGetSymbolAddress((void**)&pxs,  g_xs);
    cudaGetSymbolAddress((void**)&pws,  g_ws);

    // 0..3: small prep
    k_decode_idx<<<1, 256>>>(idx_raw, gidx_raw);
    k_gate_m<<<16, 256>>>(gate_param);
    k_gate_w<<<ROWS, 128>>>(x);
    k_fill_trig<<<dim3(256, 2), 256>>>(spectrum);

    // 4. A_p = (1/2048^2) * Pm @ Qn^T -> fp32 W2[o2][p*2048+d2]  (K'=6144)
    tgemm<<<dim3(16, 16, 2), 256>>>(
        pPms, K3T, (ll)HALF_D*K3T,
        pQns, K3T, (ll)HALF_D*K3T,
        pW2, DD, 1, HALF_D,
        nullptr, 1.0f/4194304.0f, 0, K3T);

    // 5. split fp32 operands into bf16 hi/lo K-concat form
    k_split<<<(int)(((ll)HALF_D*DD + 255)/256), 256>>>(pW2,    pW2s, (ll)HALF_D*DD, 1, 2);
    k_build_z<<<(ROWS*HALF_D)/256, 256>>>(x, Blist);
    k_split<<<(int)(((ll)ROWS*DD + 255)/256), 256>>>(x,       pxs,  (ll)ROWS*DD, 2, 1);
    k_split<<<(int)(((ll)OO*DD + 255)/256), 256>>>(base_w,    pws,  (ll)OO*DD, 1, 2);

    // 6. delta: out[row, 2n+z] = 150 * (Z_z @ W2^T)   M=8192, N=2048, K'=12288
    tgemm<<<dim3(64, 16, 2), 256>>>(
        pZs, K3, (ll)ROWS*K3,
        pW2s, K3, 0ll,
        out, OO, 2, 1,
        nullptr, 150.0f, 0, K3);

    // 7. base: out += x @ W^T + b   M=8192, N=4096, K'=12288
    tgemm<<<dim3(64, 32, 1), 256>>>(
        pxs, K3, 0ll,
        pws, K3, 0ll,
        out, OO, 1, 0,
        base_b, 1.0f, 1, K3);
}

// round 6
// speedup vs baseline: 5.3170x; 1.5017x over previous
#include <cuda_runtime.h>
#include <cuda_bf16.h>
#include <cstdint>

// ---------------------------------------------------------------------------
// KronFTLinear, bf16 mma.sync GEMMs with a tiered precision budget:
//   * base GEMM (full output magnitude)  -> bf16x3 split (fp32-like)
//   * delta path (only ~2.5e-2 of output) -> pure bf16 (errors attenuated 40x)
//
//   out = x @ W^T + b  +  150 * sum_p g_p(x) * (x @ kron(A_p, B_p)^T)
//   final[row, 2*o2+i] = 150 * sum_{p,d2} A_p[o2,d2] * Z_i[row, p*2048+d2]
//   A_p = Re ifft2(sparse) = (1/N^2) * (Pm @ Qn^T)   (trig factor GEMM)
// ---------------------------------------------------------------------------

#define DD 4096
#define OO 4096
#define HALF_D 2048
#define NFP 1000
#define ROWS 8192
#define NGATE 819
#define K3 (3*DD)        // 12288 (base GEMM split-K)

typedef long long ll;

// ---------------- device scratch (no allocation allowed) -------------------
__device__ int   g_idx32[2*NFP];
__device__ int   g_gidx32[NGATE];
__device__ float g_gate_m[2*DD];
__device__ float g_gate_w[ROWS*2];
__device__ __nv_bfloat16 g_Pms[2ll*HALF_D*HALF_D];  // trig A-factor [p][m][k]
__device__ __nv_bfloat16 g_Qns[2ll*HALF_D*HALF_D];  // trig B-factor [p][n][k]
__device__ __nv_bfloat16 g_W2s[(ll)HALF_D*DD];      // A-matrix stack, bf16 [o2][p*2048+d2]
__device__ __nv_bfloat16 g_Zs[2ll*ROWS*DD];         // gated mixed x, bf16 [i][row][p*2048+d2]
__device__ __nv_bfloat16 g_xs[(ll)ROWS*K3];         // split x  [xh|xl|xh]
__device__ __nv_bfloat16 g_ws[(ll)OO*K3];           // split base_w [wh|wh|wl]

// ---------------- PTX helpers ----------------------------------------------
__device__ __forceinline__ uint32_t smem_u32(const void* p) {
    uint32_t a;
    asm("{ .reg .u64 t; cvta.to.shared.u64 t, %1; cvt.u32.u64 %0, t; }" : "=r"(a) : "l"(p));
    return a;
}
#define CP_ASYNC16(dst, src) \
    asm volatile("cp.async.cg.shared.global [%0], [%1], 16;" :: "r"(dst), "l"(src) : "memory")
#define CP_COMMIT() asm volatile("cp.async.commit_group;" ::: "memory")

#define LDSM_X4(r0, r1, r2, r3, addr) \
    asm volatile("ldmatrix.sync.aligned.m8n8.x4.shared.b16 {%0,%1,%2,%3}, [%4];" \
        : "=r"(r0), "=r"(r1), "=r"(r2), "=r"(r3) : "r"(addr))

#define MMA16816(c, a, b) \
    asm volatile("mma.sync.aligned.m16n8k16.row.col.f32.bf16.bf16.f32 " \
        "{%0,%1,%2,%3}, {%4,%5,%6,%7}, {%8,%9}, {%0,%1,%2,%3};" \
        : "+f"((c)[0]), "+f"((c)[1]), "+f"((c)[2]), "+f"((c)[3]) \
        : "r"((a)[0]), "r"((a)[1]), "r"((a)[2]), "r"((a)[3]), \
          "r"((b)[0]), "r"((b)[1]))

// ---------------- index decode: sniff int32 vs int64 -----------------------
__global__ void k_decode_idx(const int* __restrict__ idx_raw,
                             const int* __restrict__ gidx_raw) {
    __shared__ int nz;
    if (threadIdx.x == 0) nz = 0;
    __syncthreads();
    for (int k = threadIdx.x; k < NFP/2; k += 256)
        if (idx_raw[2*k + 1] != 0) atomicAdd(&nz, 1);
    __syncthreads();
    bool is64 = (nz == 0);
    for (int k = threadIdx.x; k < 2*NFP; k += 256)
        g_idx32[k] = is64 ? idx_raw[2*k] : idx_raw[k];
    for (int k = threadIdx.x; k < NGATE; k += 256)
        g_gidx32[k] = is64 ? gidx_raw[2*k] : gidx_raw[k];
}

// ---------------- gate matrix ----------------------------------------------
__global__ void k_gate_m(const float* __restrict__ gate_param) {
    __shared__ float tab[DD];
    __shared__ int   gc[NGATE];
    __shared__ float gg[NGATE], gs[NGATE];
    for (int t = threadIdx.x; t < DD; t += 256)
        tab[t] = cospif(t * (1.0f/2048.0f));
    for (int k = threadIdx.x; k < NGATE; k += 256) {
        int v = g_gidx32[k];
        int r = v >> 12;
        gc[k] = v & 4095;
        float g = gate_param[k];
        gg[k] = g;
        gs[k] = r ? -g : g;
    }
    __syncthreads();
    int d = blockIdx.x * 256 + threadIdx.x;
    float a0 = 0.f, a1 = 0.f;
    for (int k = 0; k < NGATE; k++) {
        int t = (d * gc[k]) & 4095;
        float co = tab[t];
        a0 += gg[k] * co;
        a1 += gs[k] * co;
    }
    g_gate_m[d]      = a0 * (1.0f/8192.0f);
    g_gate_m[DD + d] = a1 * (1.0f/8192.0f);
}

// ---------------- gate weights ---------------------------------------------
__global__ void k_gate_w(const float* __restrict__ x) {
    int row = blockIdx.x;
    const float* xr = x + (ll)row * DD;
    float t0 = 0.f, t1 = 0.f;
    for (int d = threadIdx.x; d < DD; d += 128) {
        float xv = xr[d];
        t0 += xv * g_gate_m[d];
        t1 += xv * g_gate_m[DD + d];
    }
    __shared__ float s0[128], s1[128];
    s0[threadIdx.x] = t0; s1[threadIdx.x] = t1;
    __syncthreads();
    for (int o = 64; o > 0; o >>= 1) {
        if (threadIdx.x < o) {
            s0[threadIdx.x] += s0[threadIdx.x + o];
            s1[threadIdx.x] += s1[threadIdx.x + o];
        }
        __syncthreads();
    }
    if (threadIdx.x == 0) {
        float g1 = 1.0f / (1.0f + expf(-(s1[0] - s0[0])));
        g_gate_w[row*2 + 0] = 1.0f - g1;
        g_gate_w[row*2 + 1] = g1;
    }
}

// ---------------- trig factors, plain bf16 ---------------------------------
__global__ void k_fill_trig(const float* __restrict__ spectrum) {
    __shared__ float tc[HALF_D], ts[HALF_D];
    __shared__ int   rr[NFP], cc[NFP];
    __shared__ float ss[NFP];
    int p = blockIdx.y;
    for (int t = threadIdx.x; t < HALF_D; t += 256) {
        float s, c;
        sincospif(t * (1.0f/1024.0f), &s, &c);
        tc[t] = c; ts[t] = s;
    }
    for (int k = threadIdx.x; k < NFP; k += 256) {
        int v = g_idx32[p*NFP + k];
        rr[k] = v >> 11;
        cc[k] = v & 2047;
        ss[k] = spectrum[p*NFP + k];
    }
    __syncthreads();
    int v0 = blockIdx.x * 8;
    for (int vi = 0; vi < 8; vi++) {
        int v = v0 + vi;
        ll base = ((ll)(p*HALF_D + v)) * HALF_D;
        for (int k = threadIdx.x; k < NFP; k += 256) {
            int tm = (v * rr[k]) & 2047;
            int tn = (v * cc[k]) & 2047;
            float s = ss[k];
            g_Pms[base + k]       = __float2bfloat16(s * tc[tm]);
            g_Pms[base + NFP + k] = __float2bfloat16(s * ts[tm]);
            g_Qns[base + k]       = __float2bfloat16(tc[tn]);
            g_Qns[base + NFP + k] = __float2bfloat16(-ts[tn]);
        }
        for (int k = 2*NFP + threadIdx.x; k < HALF_D; k += 256) {
            __nv_bfloat16 z = __float2bfloat16(0.f);
            g_Pms[base + k] = z;
            g_Qns[base + k] = z;
        }
    }
}

// ---------------- fp32 -> split bf16 (rows of 4096, base GEMM only) --------
__global__ void k_split(const float* __restrict__ src, __nv_bfloat16* __restrict__ dst,
                        ll n, int hi2blk, int loblk) {
    ll i = (ll)blockIdx.x * 256 + threadIdx.x;
    if (i >= n) return;
    ll m = i >> 12;
    int k = (int)(i & 4095);
    float v = src[i];
    __nv_bfloat16 h = __float2bfloat16(v);
    __nv_bfloat16 l = __float2bfloat16(v - __bfloat162float(h));
    ll base = m * K3;
    dst[base + k] = h;
    dst[base + (ll)hi2blk*DD + k] = h;
    dst[base + (ll)loblk*DD + k]  = l;
}

// ---------------- Z build, plain bf16 --------------------------------------
__global__ void k_build_z(const float* __restrict__ x, const float* __restrict__ Blist) {
    ll gid = (ll)blockIdx.x * 256 + threadIdx.x;
    int row = (int)(gid >> 11);
    int d2  = (int)(gid & 2047);
    float2 xv = ((const float2*)x)[(ll)row * HALF_D + d2];
    float g0 = g_gate_w[row*2 + 0];
    float g1 = g_gate_w[row*2 + 1];
    float y00 = g0 * (Blist[0]*xv.x + Blist[1]*xv.y);   // i=0, p=0
    float y01 = g0 * (Blist[2]*xv.x + Blist[3]*xv.y);   // i=1, p=0
    float y10 = g1 * (Blist[4]*xv.x + Blist[5]*xv.y);   // i=0, p=1
    float y11 = g1 * (Blist[6]*xv.x + Blist[7]*xv.y);   // i=1, p=1
    const ll IOFF = (ll)ROWS * DD;
    ll b0 = (ll)row * DD;
    g_Zs[b0 + d2]                 = __float2bfloat16(y00);
    g_Zs[b0 + HALF_D + d2]        = __float2bfloat16(y10);
    g_Zs[IOFF + b0 + d2]          = __float2bfloat16(y01);
    g_Zs[IOFF + b0 + HALF_D + d2] = __float2bfloat16(y11);
}

// ---------------- bf16 tensor-core GEMM: C = alpha * A @ B^T (+bias)(+=C) --
// A:[M x Kp] bf16 row-major, B:[N x Kp] bf16 row-major. 128x128x32 CTA tile,
// 8 warps each computing 64x32 via mma.sync m16n8k16, cp.async double buffer.
// Output element (m,n,z) at C[m*ldc + n*cstride + z*czoff]; fp32 or bf16.
#define ASTR 40                // smem row stride in bf16 (80B, conflict-free)
#define STG_B (128*ASTR)       // bf16 elems per stage

__global__ __launch_bounds__(256, 2)
void tgemm(const __nv_bfloat16* __restrict__ A, int lda, ll sAz,
           const __nv_bfloat16* __restrict__ B, int ldb, ll sBz,
           void* __restrict__ Cv, int ldc, int cstride, int czoff,
           const float* __restrict__ bias, float alpha, int accumulate,
           int Kp, int out_bf16)
{
    __shared__ __nv_bfloat16 sA[2*STG_B];
    __shared__ __nv_bfloat16 sB[2*STG_B];
    uint32_t aB = smem_u32(sA), bB = smem_u32(sB);
    int tid = threadIdx.x, wid = tid >> 5, lane = tid & 31;
    int warpM = wid >> 2;          // 0..1  (64 rows)
    int warpN = wid & 3;           // 0..3  (32 cols)
    int z = blockIdx.z;
    ll m0 = (ll)blockIdx.x * 128;
    ll n0 = (ll)blockIdx.y * 128;
    const __nv_bfloat16* Ab = A + (ll)z*sAz + m0*lda;
    const __nv_bfloat16* Bb = B + (ll)z*sBz + n0*ldb;

    float acc[4][4][4];
    #pragma unroll
    for (int i = 0; i < 4; i++)
        #pragma unroll
        for (int j = 0; j < 4; j++)
            #pragma unroll
            for (int q = 0; q < 4; q++) acc[i][j][q] = 0.f;

    int ldr = tid >> 2;
    int ldc8 = (tid & 3) * 8;

    int aRow = warpM*64 + (lane & 15);
    int aCsel = (lane >> 4) * 8;
    int bRowOff = (lane & 7) + ((lane >> 4) << 3);
    int bCsel = ((lane >> 3) & 1) * 8;

    int NP = Kp >> 5;

    {
        uint32_t da = aB + ldr*80 + ldc8*2;
        uint32_t db = bB + ldr*80 + ldc8*2;
        CP_ASYNC16(da,        Ab + (ll)ldr*lda + ldc8);
        CP_ASYNC16(db,        Bb + (ll)ldr*ldb + ldc8);
        CP_ASYNC16(da + 64*80, Ab + (ll)(ldr+64)*lda + ldc8);
        CP_ASYNC16(db + 64*80, Bb + (ll)(ldr+64)*ldb + ldc8);
        CP_COMMIT();
    }

    for (int kc = 0; kc < NP; kc++) {
        int st = kc & 1;
        if (kc + 1 < NP) {
            int k0 = (kc + 1) * 32;
            uint32_t so = ((kc + 1) & 1) * (STG_B*2);
            uint32_t da = aB + so + ldr*80 + ldc8*2;
            uint32_t db = bB + so + ldr*80 + ldc8*2;
            CP_ASYNC16(da,        Ab + (ll)ldr*lda + k0 + ldc8);
            CP_ASYNC16(db,        Bb + (ll)ldr*ldb + k0 + ldc8);
            CP_ASYNC16(da + 64*80, Ab + (ll)(ldr+64)*lda + k0 + ldc8);
            CP_ASYNC16(db + 64*80, Bb + (ll)(ldr+64)*ldb + k0 + ldc8);
            CP_COMMIT();
            asm volatile("cp.async.wait_group 1;" ::: "memory");
        } else {
            asm volatile("cp.async.wait_group 0;" ::: "memory");
        }
        __syncthreads();

        uint32_t sao = aB + st * (STG_B*2);
        uint32_t sbo = bB + st * (STG_B*2);
        #pragma unroll
        for (int ks = 0; ks < 32; ks += 16) {
            uint32_t af[4][4];
            #pragma unroll
            for (int mi = 0; mi < 4; mi++) {
                uint32_t ad = sao + (uint32_t)(aRow + mi*16)*80 + (uint32_t)(ks + aCsel)*2;
                LDSM_X4(af[mi][0], af[mi][1], af[mi][2], af[mi][3], ad);
            }
            uint32_t bf[4][2];
            #pragma unroll
            for (int nj = 0; nj < 2; nj++) {
                uint32_t bd = sbo + (uint32_t)(warpN*32 + nj*16 + bRowOff)*80
                                  + (uint32_t)(ks + bCsel)*2;
                uint32_t r0, r1, r2, r3;
                LDSM_X4(r0, r1, r2, r3, bd);
                bf[nj*2][0] = r0; bf[nj*2][1] = r1;
                bf[nj*2+1][0] = r2; bf[nj*2+1][1] = r3;
            }
            #pragma unroll
            for (int mi = 0; mi < 4; mi++)
                #pragma unroll
                for (int ni = 0; ni < 4; ni++)
                    MMA16816(acc[mi][ni], af[mi], bf[ni]);
        }
        __syncthreads();
    }

    // epilogue
    int gID = lane >> 2, tig = lane & 3;
    #pragma unroll
    for (int mi = 0; mi < 4; mi++) {
        #pragma unroll
        for (int h = 0; h < 2; h++) {
            ll row = m0 + warpM*64 + mi*16 + gID + h*8;
            ll rbase = row * (ll)ldc + (ll)z * czoff;
            #pragma unroll
            for (int ni = 0; ni < 4; ni++) {
                ll col0 = n0 + warpN*32 + ni*8 + tig*2;
                #pragma unroll
                for (int q = 0; q < 2; q++) {
                    ll col = col0 + q;
                    float v = acc[mi][ni][h*2 + q] * alpha;
                    if (bias) v += bias[col];
                    ll off = rbase + col * cstride;
                    if (out_bf16) {
                        ((__nv_bfloat16*)Cv)[off] = __float2bfloat16(v);
                    } else {
                        float* cp = (float*)Cv + off;
                        if (accumulate) v += *cp;
                        *cp = v;
                    }
                }
            }
        }
    }
}

// ---------------------------------------------------------------------------
extern "C" void kernel_launch(void* const* d_in, const int* in_sizes, int n_in,
                              void* d_out, int out_size) {
    const float* x          = (const float*)d_in[0];
    const float* base_w     = (const float*)d_in[1];
    const float* base_b     = (const float*)d_in[2];
    const float* spectrum   = (const float*)d_in[3];
    const float* Blist      = (const float*)d_in[4];
    const float* gate_param = (const float*)d_in[5];
    const int*   idx_raw    = (const int*)d_in[6];
    const int*   gidx_raw   = (const int*)d_in[7];
    float* out = (float*)d_out;
    (void)in_sizes; (void)n_in; (void)out_size;

    __nv_bfloat16 *pPms, *pQns, *pW2s, *pZs, *pxs, *pws;
    cudaGetSymbolAddress((void**)&pPms, g_Pms);
    cudaGetSymbolAddress((void**)&pQns, g_Qns);
    cudaGetSymbolAddress((void**)&pW2s, g_W2s);
    cudaGetSymbolAddress((void**)&pZs,  g_Zs);
    cudaGetSymbolAddress((void**)&pxs,  g_xs);
    cudaGetSymbolAddress((void**)&pws,  g_ws);

    // 0..3: small prep
    k_decode_idx<<<1, 256>>>(idx_raw, gidx_raw);
    k_gate_m<<<16, 256>>>(gate_param);
    k_gate_w<<<ROWS, 128>>>(x);
    k_fill_trig<<<dim3(256, 2), 256>>>(spectrum);

    // 4. A_p = (1/2048^2) * Pm @ Qn^T -> bf16 W2s[o2][p*2048+d2]  (K=2048)
    tgemm<<<dim3(16, 16, 2), 256>>>(
        pPms, HALF_D, (ll)HALF_D*HALF_D,
        pQns, HALF_D, (ll)HALF_D*HALF_D,
        pW2s, DD, 1, HALF_D,
        nullptr, 1.0f/4194304.0f, 0, HALF_D, 1);

    // 5. splits + Z (base GEMM operands split, delta operands plain bf16)
    k_build_z<<<(ROWS*HALF_D)/256, 256>>>(x, Blist);
    k_split<<<(int)(((ll)ROWS*DD + 255)/256), 256>>>(x,      pxs, (ll)ROWS*DD, 2, 1);
    k_split<<<(int)(((ll)OO*DD + 255)/256), 256>>>(base_w,   pws, (ll)OO*DD, 1, 2);

    // 6. delta: out[row, 2n+z] = 150 * (Z_z @ W2s^T)  M=8192, N=2048, K=4096
    tgemm<<<dim3(64, 16, 2), 256>>>(
        pZs, DD, (ll)ROWS*DD,
        pW2s, DD, 0ll,
        out, OO, 2, 1,
        nullptr, 150.0f, 0, DD, 0);

    // 7. base: out += x @ W^T + b   M=8192, N=4096, K'=12288 (bf16x3 split)
    tgemm<<<dim3(64, 32, 1), 256>>>(
        pxs, K3, 0ll,
        pws, K3, 0ll,
        out, OO, 1, 0,
        base_b, 1.0f, 1, K3, 0);
}